// round 11
// baseline (speedup 1.0000x reference)
#include <cuda_runtime.h>
#include <cstdint>

// cAttend_simple, third algebraic form (histogram + dense streaming):
//   h_b[p]   = sum_{i: pos[b,i]=p} val[b,i]          (scatter, 16K atomics)
//   u_b      = sum_p h_b[p] * embed[p]               (coalesced stream #1)
//   V_b      = sum_p h_b[p]
//   s_b = Wq u_b + bq V_b;  w_b = Wk^T s_b;  c_b = s_b . bk   (tiny)
//   z_b[p]   = w_b . embed[p]                        (coalesced stream #2)
//   out[b,j] = val[b,j] * (1 + SCALE*(z_b[pos[b,j]] + c_b))   (16K lookups)
// No random 1KB-row gathers anywhere; embed is read twice, fully coalesced.

#define BB 4
#define NN 4096
#define EE 256
#define DD 64
#define PP 10001           // DATA_DIM + 1 embed rows
#define SCALE 0.125f       // 64^{-1/2}
#define K2BLK 128
#define K3BLK 128

// __device__ scratch (allocation-free rule)
__device__ float    g_h[PP * BB];       // h[p*4 + b]
__device__ float    g_z[PP * BB];       // z[p*4 + b]
__device__ float    g_u[BB * EE];       // u[b*256 + col]  (atomic-accumulated)
__device__ float    g_V[BB];
__device__ float    g_w[BB][EE];
__device__ float    g_c[BB];
__device__ unsigned g_c2, g_c3;         // last-block counters (reset in K0)

__device__ __forceinline__ float ldcg(const float* p) {
    float r;
    asm volatile("ld.global.cg.f32 %0, [%1];" : "=f"(r) : "l"(p));
    return r;
}

// ---------------------------------------------------------------------------
// K0: zero h, u, V; reset counters.  (graph-replay safe reset point)
// ---------------------------------------------------------------------------
__global__ void __launch_bounds__(1024) k_zero() {
    const int i = blockIdx.x * 1024 + threadIdx.x;
    if (i < PP * BB) g_h[i] = 0.f;
    if (i < BB * EE) g_u[i] = 0.f;
    if (i == 0) {
        g_V[0] = g_V[1] = g_V[2] = g_V[3] = 0.f;
        g_c2 = 0; g_c3 = 0;
    }
}

// ---------------------------------------------------------------------------
// K1: histogram scatter.  16384 spread atomicAdds (mostly distinct addrs).
// ---------------------------------------------------------------------------
__global__ void __launch_bounds__(1024) k_hist(const float* __restrict__ val,
                                               const int* __restrict__ pos) {
    const int i = blockIdx.x * 1024 + threadIdx.x;   // i = b*NN + j
    if (i < BB * NN) {
        const int b = i >> 12;
        atomicAdd(&g_h[(size_t)pos[i] * BB + b], val[i]);
    }
}

// ---------------------------------------------------------------------------
// K2: stream embed once -> u partial (atomic combine), V partial;
//     last block does the tiny projection -> g_w, g_c.
// grid K2BLK x 1024.  thread t: batch b = t>>8, column col = t&255.
// ---------------------------------------------------------------------------
__global__ void __launch_bounds__(1024, 1)
k_stream_u(const float* __restrict__ embed, const float* __restrict__ Wq,
           const float* __restrict__ bq, const float* __restrict__ Wk,
           const float* __restrict__ bk) {
    const int t    = threadIdx.x;
    const int blk  = blockIdx.x;
    const int b    = t >> 8;
    const int col  = t & 255;
    const int warp = t >> 5;
    const int lane = t & 31;

    float acc = 0.f, vacc = 0.f;
#pragma unroll 4
    for (int p = blk; p < PP; p += K2BLK) {
        const float hv = ldcg(&g_h[(size_t)p * BB + b]);      // L2-coherent, warp-uniform
        acc += hv * __ldg(&embed[(size_t)p * EE + col]);      // coalesced
        vacc += hv;
    }
    atomicAdd(&g_u[t], acc);                 // per-thread-distinct address
    if (col == 0) atomicAdd(&g_V[b], vacc);

    __threadfence();
    __syncthreads();
    __shared__ unsigned is_last;
    if (t == 0) is_last = (atomicAdd(&g_c2, 1) == K2BLK - 1) ? 1u : 0u;
    __syncthreads();
    if (!is_last) return;
    __threadfence();

    // ---- projection (one block, trivial flops) ----
    __shared__ float su[BB][EE];
    __shared__ float ss[BB][DD];
    __shared__ float sV[BB];
    su[b][col] = ldcg(&g_u[t]);              // L2-coherent read of atomic results
    if (warp < BB && lane == 0) sV[warp] = ldcg(&g_V[warp]);
    __syncthreads();

    // s[b][d] = Wq[d,:].u_b + bq[d]*V_b ; batch b's 8 warps cover d
    {
        const int wg = warp & 7;              // warp within batch group
#pragma unroll
        for (int d = wg; d < DD; d += 8) {
            float a = 0.f;
#pragma unroll
            for (int e = lane; e < EE; e += 32) a += __ldg(&Wq[d * EE + e]) * su[b][e];
#pragma unroll
            for (int o = 16; o; o >>= 1) a += __shfl_xor_sync(0xffffffffu, a, o);
            if (lane == 0) ss[b][d] = a + __ldg(&bq[d]) * sV[b];
        }
    }
    __syncthreads();

    // w[b][col] = sum_d Wk[d][col]*s[b][d]
    {
        float w = 0.f;
#pragma unroll 8
        for (int d = 0; d < DD; d++) w += __ldg(&Wk[d * EE + col]) * ss[b][d];
        g_w[b][col] = w;
    }
    // c[b] = s_b . bk   (warps 0..3)
    if (warp < BB) {
        float c = ss[warp][lane] * __ldg(&bk[lane])
                + ss[warp][lane + 32] * __ldg(&bk[lane + 32]);
#pragma unroll
        for (int o = 16; o; o >>= 1) c += __shfl_xor_sync(0xffffffffu, c, o);
        if (lane == 0) g_c[warp] = c;
    }
}

// ---------------------------------------------------------------------------
// K3: stream embed again -> z[p][b] (one warp per row);
//     last block does the 16K output lookups.
// grid K3BLK x 1024 (32 warps/block -> 4096 concurrent warps).
// ---------------------------------------------------------------------------
__global__ void __launch_bounds__(1024, 1)
k_z_out(const float* __restrict__ val, const int* __restrict__ pos,
        const float* __restrict__ embed, float* __restrict__ out) {
    const int t    = threadIdx.x;
    const int blk  = blockIdx.x;
    const int warp = t >> 5;
    const int lane = t & 31;

    __shared__ float sw[BB][EE];
    __shared__ float sc[BB];
    sw[t >> 8][t & 255] = ldcg(&g_w[t >> 8][t & 255]);  // written by prev kernel
    if (t < BB) sc[t] = ldcg(&g_c[t]);
    __syncthreads();

    // hoist all 4 batches' w into registers (8 float4 = 32 regs)
    const float4 w00 = ((const float4*)sw[0])[lane], w01 = ((const float4*)sw[0])[lane + 32];
    const float4 w10 = ((const float4*)sw[1])[lane], w11 = ((const float4*)sw[1])[lane + 32];
    const float4 w20 = ((const float4*)sw[2])[lane], w21 = ((const float4*)sw[2])[lane + 32];
    const float4 w30 = ((const float4*)sw[3])[lane], w31 = ((const float4*)sw[3])[lane + 32];

    for (int p = blk * 32 + warp; p < PP; p += K3BLK * 32) {
        const float4* er = (const float4*)(embed + (size_t)p * EE);
        const float4 a0 = __ldg(&er[lane]);
        const float4 a1 = __ldg(&er[lane + 32]);
        float d0 = a0.x*w00.x + a0.y*w00.y + a0.z*w00.z + a0.w*w00.w
                 + a1.x*w01.x + a1.y*w01.y + a1.z*w01.z + a1.w*w01.w;
        float d1 = a0.x*w10.x + a0.y*w10.y + a0.z*w10.z + a0.w*w10.w
                 + a1.x*w11.x + a1.y*w11.y + a1.z*w11.z + a1.w*w11.w;
        float d2 = a0.x*w20.x + a0.y*w20.y + a0.z*w20.z + a0.w*w20.w
                 + a1.x*w21.x + a1.y*w21.y + a1.z*w21.z + a1.w*w21.w;
        float d3 = a0.x*w30.x + a0.y*w30.y + a0.z*w30.z + a0.w*w30.w
                 + a1.x*w31.x + a1.y*w31.y + a1.z*w31.z + a1.w*w31.w;
#pragma unroll
        for (int o = 16; o; o >>= 1) {
            d0 += __shfl_xor_sync(0xffffffffu, d0, o);
            d1 += __shfl_xor_sync(0xffffffffu, d1, o);
            d2 += __shfl_xor_sync(0xffffffffu, d2, o);
            d3 += __shfl_xor_sync(0xffffffffu, d3, o);
        }
        if (lane == 0) {
            ((float4*)g_z)[p] = make_float4(d0, d1, d2, d3);
        }
    }

    __threadfence();
    __syncthreads();
    __shared__ unsigned is_last;
    if (t == 0) is_last = (atomicAdd(&g_c3, 1) == K3BLK - 1) ? 1u : 0u;
    __syncthreads();
    if (!is_last) return;
    __threadfence();

    // ---- output lookups: 16K z reads (L2-hot 160KB, ld.cg for coherence) ----
#pragma unroll 4
    for (int i = t; i < BB * NN; i += 1024) {
        const int b = i >> 12;
        const int p = __ldg(&pos[i]);
        const float z = ldcg(&g_z[(size_t)p * BB + b]);
        const float v = __ldg(&val[i]);
        out[i] = v + v * (SCALE * (z + sc[b]));
    }
}

// ---------------------------------------------------------------------------
extern "C" void kernel_launch(void* const* d_in, const int* in_sizes, int n_in,
                              void* d_out, int out_size) {
    // metadata order: t, val, pos, embed, Wq, bq, Wk, bk
    const int base = n_in - 7;
    const float* val   = (const float*)d_in[base + 0];
    const int*   pos   = (const int*)  d_in[base + 1];
    const float* embed = (const float*)d_in[base + 2];
    const float* Wq    = (const float*)d_in[base + 3];
    const float* bq    = (const float*)d_in[base + 4];
    const float* Wk    = (const float*)d_in[base + 5];
    const float* bk    = (const float*)d_in[base + 6];
    float* out = (float*)d_out;

    k_zero<<<(PP * BB + 1023) / 1024, 1024>>>();
    k_hist<<<(BB * NN + 1023) / 1024, 1024>>>(val, pos);
    k_stream_u<<<K2BLK, 1024>>>(embed, Wq, bq, Wk, bk);
    k_z_out<<<K3BLK, 1024>>>(val, pos, embed, out);
}